// round 10
// baseline (speedup 1.0000x reference)
#include <cuda_runtime.h>
#include <cuda_bf16.h>
#include <math.h>
#include <stdint.h>

// Problem constants
#define BB   64
#define TT   512
#define EE   128
#define HH   256
#define HP   128
#define KK   32
#define SOS  2
#define EOS  3

// LSTM recurrence split: KS h-slices of wh in smem (bf16), TAILK in registers (fp32)
#define KS    48
#define TAILK 80
#define LSTM_SMEM (KS*512*2 + (512 + 128) * 4)

typedef unsigned long long ull;

__device__ __forceinline__ ull fma2(ull a, ull b, ull c) {
    ull d;
    asm("fma.rn.f32x2 %0, %1, %2, %3;" : "=l"(d) : "l"(a), "l"(b), "l"(c));
    return d;
}
__device__ __forceinline__ ull add2(ull a, ull b) {
    ull d;
    asm("add.rn.f32x2 %0, %1, %2;" : "=l"(d) : "l"(a), "l"(b));
    return d;
}
__device__ __forceinline__ float2 unpack2(ull a) {
    float2 r;
    asm("mov.b64 {%0, %1}, %2;" : "=f"(r.x), "=f"(r.y) : "l"(a));
    return r;
}
// packed (bf16 lo, bf16 hi) -> f32x2 pair (exact: bf16 is top 16 bits of f32)
__device__ __forceinline__ ull bf2up(uint32_t r) {
    ull d;
    asm("{ .reg .b32 lo, hi;\n\t"
        "  shl.b32 lo, %1, 16;\n\t"
        "  and.b32 hi, %1, 0xFFFF0000;\n\t"
        "  mov.b64 %0, {lo, hi}; }"
        : "=l"(d) : "r"(r));
    return d;
}

// ---------------- device scratch ----------------
__device__ float g_G [ (size_t)BB * TT * 1024 ];   // gate preactivations, both dirs
__device__ float g_H0[ (size_t)BB * TT * 256 ];
__device__ float g_H1[ (size_t)BB * TT * 256 ];
__device__ float g_E [ (size_t)BB * TT * 32 ];
__device__ float g_whR[ 4 * 512 * 128 ];           // [dl][row][k] (verbatim wh copies)
__device__ float g_wi0[ 1024 * 128 ];
__device__ float g_wi1[ 1024 * 256 ];
__device__ float g_b0 [ 1024 ];
__device__ float g_b1 [ 1024 ];
__device__ int   g_len[ BB ];

// ---------------- lengths ----------------
__global__ void len_kernel(const int* __restrict__ x)
{
    int b = blockIdx.x;
    __shared__ int cnt;
    if (threadIdx.x == 0) cnt = 0;
    __syncthreads();
    int local = 0;
    for (int t = threadIdx.x; t < TT; t += blockDim.x)
        local += (x[b * TT + t] > 0) ? 1 : 0;
    atomicAdd(&cnt, local);
    __syncthreads();
    if (threadIdx.x == 0) g_len[b] = cnt;
}

// ---------------- weight packing ----------------
__global__ void pack_kernel(const float* __restrict__ wi0f, const float* __restrict__ wi0b,
                            const float* __restrict__ b0f,  const float* __restrict__ b0b,
                            const float* __restrict__ wi1f, const float* __restrict__ wi1b,
                            const float* __restrict__ b1f,  const float* __restrict__ b1b,
                            const float* __restrict__ wh0f, const float* __restrict__ wh0b,
                            const float* __restrict__ wh1f, const float* __restrict__ wh1b)
{
    int tid = blockIdx.x * blockDim.x + threadIdx.x;
    int stride = gridDim.x * blockDim.x;
    for (int i = tid; i < 512 * 128; i += stride) {
        g_wi0[i]             = wi0f[i];
        g_wi0[512 * 128 + i] = wi0b[i];
    }
    for (int i = tid; i < 512 * 256; i += stride) {
        g_wi1[i]             = wi1f[i];
        g_wi1[512 * 256 + i] = wi1b[i];
    }
    for (int i = tid; i < 512; i += stride) {
        g_b0[i]       = b0f[i];
        g_b0[512 + i] = b0b[i];
        g_b1[i]       = b1f[i];
        g_b1[512 + i] = b1b[i];
    }
    const float* whs[4] = { wh0f, wh0b, wh1f, wh1b };
    for (int dl = 0; dl < 4; ++dl) {
        const float* w = whs[dl];
        for (int i = tid; i < 512 * 128; i += stride)
            g_whR[dl * 65536 + i] = w[i];
    }
}

// ---------------- fp32 GEMM (R1): C[m][n] = sum_k A[m][k]*B[n][k] + bias[n] ----------------
// Skips blocks whose entire t-range is padding (output never consumed).
__global__ void gemm_kernel(const float* __restrict__ Ain, const int* __restrict__ gidx,
                            int Kd, int phase)
{
    __shared__ float As[16][68];
    __shared__ float Bs[16][68];

    int m0 = blockIdx.y * 64;
    int n0 = blockIdx.x * 64;

    {
        int b  = m0 >> 9;
        int t0 = m0 & 511;
        if (t0 >= g_len[b]) return;   // uniform across CTA, before any barrier
    }

    const float* A    = phase ? g_H0  : Ain;
    const float* Bw   = phase ? g_wi1 : g_wi0;
    const float* bias = phase ? g_b1  : g_b0;

    int tid = threadIdx.x;
    int lm = tid >> 2;
    int lk = (tid & 3) * 4;

    int arow_idx = m0 + lm;
    const float* arow = A  + (size_t)(gidx ? gidx[arow_idx] : arow_idx) * Kd;
    const float* brow = Bw + (size_t)(n0 + lm) * Kd;

    int tm = tid & 15;
    int tn = tid >> 4;

    float acc[4][4] = {};

    for (int k0 = 0; k0 < Kd; k0 += 16) {
        float4 av = *(const float4*)(arow + k0 + lk);
        float4 bv = *(const float4*)(brow + k0 + lk);
        __syncthreads();
        As[lk + 0][lm] = av.x; As[lk + 1][lm] = av.y;
        As[lk + 2][lm] = av.z; As[lk + 3][lm] = av.w;
        Bs[lk + 0][lm] = bv.x; Bs[lk + 1][lm] = bv.y;
        Bs[lk + 2][lm] = bv.z; Bs[lk + 3][lm] = bv.w;
        __syncthreads();
#pragma unroll
        for (int kk = 0; kk < 16; ++kk) {
            float4 a = *(const float4*)&As[kk][tm * 4];
            float4 b = *(const float4*)&Bs[kk][tn * 4];
            acc[0][0] += a.x * b.x; acc[0][1] += a.x * b.y; acc[0][2] += a.x * b.z; acc[0][3] += a.x * b.w;
            acc[1][0] += a.y * b.x; acc[1][1] += a.y * b.y; acc[1][2] += a.y * b.z; acc[1][3] += a.y * b.w;
            acc[2][0] += a.z * b.x; acc[2][1] += a.z * b.y; acc[2][2] += a.z * b.z; acc[2][3] += a.z * b.w;
            acc[3][0] += a.w * b.x; acc[3][1] += a.w * b.y; acc[3][2] += a.w * b.z; acc[3][3] += a.w * b.w;
        }
    }

    float4 bo = *(const float4*)&bias[n0 + tn * 4];
#pragma unroll
    for (int i = 0; i < 4; ++i) {
        int m = m0 + tm * 4 + i;
        float4 r;
        r.x = acc[i][0] + bo.x; r.y = acc[i][1] + bo.y;
        r.z = acc[i][2] + bo.z; r.w = acc[i][3] + bo.w;
        *(float4*)&g_G[(size_t)m * 1024 + n0 + tn * 4] = r;
    }
}

// ---------------- LSTM recurrence: k-paired f32x2, plain h (no duplication) ----------------
__device__ __forceinline__ float tanh_mufu(float x) {
    float r;
    asm("tanh.approx.f32 %0, %1;" : "=f"(r) : "f"(x));
    return r;
}
__device__ __forceinline__ float sigm(float x) {
    return fmaf(0.5f, tanh_mufu(0.5f * x), 0.5f);
}

__global__ void __launch_bounds__(256, 1) lstm_kernel(int layer)
{
    int b   = blockIdx.x;
    int dir = blockIdx.y;
    const float* whR = g_whR + (size_t)(layer * 2 + dir) * 65536;  // [row][k]

    extern __shared__ float sm[];
    uint32_t* pwsb = (uint32_t*)sm;            // KS*256 u32: bf16 (k,k+1) pairs, 2 rows/thread
    float* zbuf = sm + (KS * 512 * 2) / 4;     // 512
    float* h_sm = zbuf + 512;                  // 128 (plain h)

    int tid = threadIdx.x;
    int r0 = 2 * tid, r1 = 2 * tid + 1;

    // smem bf16 weights: chunk c = k-slices 4c..4c+3 of this thread's two rows
    for (int c = 0; c < KS / 4; ++c) {
        float4 w0 = *(const float4*)&whR[r0 * 128 + 4 * c];
        float4 w1 = *(const float4*)&whR[r1 * 128 + 4 * c];
        __nv_bfloat162 p0 = __float22bfloat162_rn(make_float2(w0.x, w0.y));
        __nv_bfloat162 p1 = __float22bfloat162_rn(make_float2(w0.z, w0.w));
        __nv_bfloat162 p2 = __float22bfloat162_rn(make_float2(w1.x, w1.y));
        __nv_bfloat162 p3 = __float22bfloat162_rn(make_float2(w1.z, w1.w));
        *(uint4*)&pwsb[(c * 256 + tid) * 4] =
            make_uint4(*(uint32_t*)&p0, *(uint32_t*)&p1, *(uint32_t*)&p2, *(uint32_t*)&p3);
    }

    // register tail (fp32): k-pairs KS/2..63 for both rows
    ull tw0[TAILK / 2], tw1[TAILK / 2];
#pragma unroll
    for (int j = 0; j < TAILK / 2; ++j) {
        tw0[j] = *(const ull*)&whR[r0 * 128 + KS + 2 * j];
        tw1[j] = *(const ull*)&whR[r1 * 128 + KS + 2 * j];
    }

    if (tid < 128) h_sm[tid] = 0.f;
    float c_st = 0.f;
    int len = g_len[b];
    float* Hout = layer ? g_H1 : g_H0;
    __syncthreads();

    const ulonglong2* hq  = (const ulonglong2*)h_sm;           // 4 h per load
    const ulonglong2* hqt = (const ulonglong2*)&h_sm[KS];      // tail part

    int t = (dir == 0) ? 0 : (len - 1);
    ull gc = *(const ull*)&g_G[((size_t)(b * TT + t)) * 1024 + dir * 512 + 2 * tid];

    for (int s = 0; s < len; ++s) {
        int sn = s + 1;
        int tnx;
        if (dir == 0) tnx = sn;
        else          tnx = len - 1 - sn;
        if (sn >= len) tnx = t;   // dummy (value unused on last iter)
        ull gn = *(const ull*)&g_G[((size_t)(b * TT + tnx)) * 1024 + dir * 512 + 2 * tid];

        ull a0 = 0, a1 = 0, b0 = 0, b1 = 0;   // a* = row r0, b* = row r1
#pragma unroll
        for (int c = 0; c < KS / 4; ++c) {
            uint4 w4 = *(const uint4*)&pwsb[(c * 256 + tid) * 4];
            ulonglong2 hu = hq[c];
            a0 = fma2(bf2up(w4.x), hu.x, a0);
            a1 = fma2(bf2up(w4.y), hu.y, a1);
            b0 = fma2(bf2up(w4.z), hu.x, b0);
            b1 = fma2(bf2up(w4.w), hu.y, b1);
        }
#pragma unroll
        for (int j2 = 0; j2 < TAILK / 4; ++j2) {
            ulonglong2 hu = hqt[j2];
            a0 = fma2(tw0[2 * j2],     hu.x, a0);
            a1 = fma2(tw0[2 * j2 + 1], hu.y, a1);
            b0 = fma2(tw1[2 * j2],     hu.x, b0);
            b1 = fma2(tw1[2 * j2 + 1], hu.y, b1);
        }
        float2 s0 = unpack2(add2(a0, a1));
        float2 s1 = unpack2(add2(b0, b1));
        float2 g  = unpack2(gc);
        *(float2*)&zbuf[2 * tid] = make_float2(g.x + s0.x + s0.y, g.y + s1.x + s1.y);
        __syncthreads();

        if (tid < 128) {
            float zi = zbuf[tid],       zf = zbuf[128 + tid];
            float zg = zbuf[256 + tid], zo = zbuf[384 + tid];
            c_st = sigm(zf) * c_st + sigm(zi) * tanh_mufu(zg);
            float h = sigm(zo) * tanh_mufu(c_st);
            h_sm[tid] = h;
            Hout[((size_t)(b * TT + t)) * 256 + dir * 128 + tid] = h;
        }
        __syncthreads();
        gc = gn;
        t  = tnx;
    }
}

// ---------------- emissions: e = H1 @ w_out^T + b_out ----------------
__global__ void emis_kernel(const float* __restrict__ w_out, const float* __restrict__ b_out)
{
    __shared__ float ws[32 * 257];
    __shared__ float hs[8][256];
    __shared__ float bs[32];

    int tid = threadIdx.x;
    for (int i = tid; i < 32 * 256; i += 256)
        ws[(i >> 8) * 257 + (i & 255)] = w_out[i];
    if (tid < 32) bs[tid] = b_out[tid];

    int w    = tid >> 5;
    int lane = tid & 31;
    int m    = blockIdx.x * 8 + w;
    for (int d = lane; d < 256; d += 32)
        hs[w][d] = g_H1[(size_t)m * 256 + d];
    __syncthreads();

    float e = bs[lane];
#pragma unroll 8
    for (int d = 0; d < 256; ++d)
        e += hs[w][d] * ws[lane * 257 + d];
    g_E[(size_t)m * 32 + lane] = e;
}

// ---------------- CRF: warp per batch ----------------
__global__ void crf_kernel(const int* __restrict__ y, const float* __restrict__ trans,
                           float* __restrict__ out)
{
    int b    = blockIdx.x;
    int lane = threadIdx.x;
    __shared__ float tr[32 * 33];
    for (int i = lane; i < 1024; i += 32)
        tr[(i >> 5) * 33 + (i & 31)] = trans[i];
    __syncwarp();

    int len = g_len[b];
    const float* Eb = g_E + (size_t)b * TT * 32;

    float score = (lane == SOS) ? 0.f : -10000.f;
    for (int t = 0; t < len; ++t) {
        float e = Eb[t * 32 + lane];
        float v[32];
#pragma unroll
        for (int k = 0; k < 32; ++k)
            v[k] = __shfl_sync(0xffffffffu, score, k) + tr[lane * 33 + k];
        float m = v[0];
#pragma unroll
        for (int k = 1; k < 32; ++k) m = fmaxf(m, v[k]);
        float s = 0.f;
#pragma unroll
        for (int k = 0; k < 32; ++k) s += expf(v[k] - m);
        score = e + m + logf(s);
    }

    float v2 = score + tr[EOS * 33 + lane];
    float m = v2;
#pragma unroll
    for (int off = 16; off; off >>= 1) m = fmaxf(m, __shfl_xor_sync(0xffffffffu, m, off));
    float s = expf(v2 - m);
#pragma unroll
    for (int off = 16; off; off >>= 1) s += __shfl_xor_sync(0xffffffffu, s, off);
    float logZ = m + logf(s);

    const int* yb = y + b * (TT + 1);
    float g = 0.f;
    for (int t = lane; t < len; t += 32) {
        int y1 = yb[t + 1];
        int y0 = yb[t];
        g += Eb[t * 32 + y1] + tr[y1 * 33 + y0];
    }
#pragma unroll
    for (int off = 16; off; off >>= 1) g += __shfl_xor_sync(0xffffffffu, g, off);

    if (lane == 0) {
        g += tr[EOS * 33 + yb[len]];
        out[b] = logZ - g;
    }
}

// ---------------- launch ----------------
extern "C" void kernel_launch(void* const* d_in, const int* in_sizes, int n_in,
                              void* d_out, int out_size)
{
    const int*   x      = (const int*)  d_in[0];
    const int*   y      = (const int*)  d_in[1];
    const float* embed  = (const float*)d_in[2];
    const float* wi_l0f = (const float*)d_in[3];
    const float* wh_l0f = (const float*)d_in[4];
    const float* b_l0f  = (const float*)d_in[5];
    const float* wi_l0b = (const float*)d_in[6];
    const float* wh_l0b = (const float*)d_in[7];
    const float* b_l0b  = (const float*)d_in[8];
    const float* wi_l1f = (const float*)d_in[9];
    const float* wh_l1f = (const float*)d_in[10];
    const float* b_l1f  = (const float*)d_in[11];
    const float* wi_l1b = (const float*)d_in[12];
    const float* wh_l1b = (const float*)d_in[13];
    const float* b_l1b  = (const float*)d_in[14];
    const float* w_out  = (const float*)d_in[15];
    const float* b_out  = (const float*)d_in[16];
    const float* trans  = (const float*)d_in[17];
    float* out = (float*)d_out;

    cudaFuncSetAttribute(lstm_kernel, cudaFuncAttributeMaxDynamicSharedMemorySize, LSTM_SMEM);

    len_kernel<<<BB, 256>>>(x);
    pack_kernel<<<256, 256>>>(wi_l0f, wi_l0b, b_l0f, b_l0b,
                              wi_l1f, wi_l1b, b_l1f, b_l1b,
                              wh_l0f, wh_l0b, wh_l1f, wh_l1b);

    gemm_kernel<<<dim3(16, 512), 256>>>(embed, x, 128, 0);
    lstm_kernel<<<dim3(BB, 2), 256, LSTM_SMEM>>>(0);

    gemm_kernel<<<dim3(16, 512), 256>>>(nullptr, nullptr, 256, 1);
    lstm_kernel<<<dim3(BB, 2), 256, LSTM_SMEM>>>(1);

    emis_kernel<<<(BB * TT) / 8, 256>>>(w_out, b_out);
    crf_kernel<<<BB, 32>>>(y, trans, out);
}

// round 11
// speedup vs baseline: 1.4045x; 1.4045x over previous
#include <cuda_runtime.h>
#include <cuda_bf16.h>
#include <math.h>
#include <stdint.h>

// Problem constants
#define BB   64
#define TT   512
#define EE   128
#define HH   256
#define HP   128
#define KK   32
#define SOS  2
#define EOS  3

// LSTM recurrence split: KS h-slices of wh in smem (bf16), TAILK in registers (fp32)
#define KS    48
#define TAILK 80
#define LSTM_SMEM (KS*512*2 + (512 + 256) * 4)

// GEMM tile smem: two 64x128 tiles padded to 132 words/row
#define GEMM_SMEM (2 * 64 * 132 * 4)

typedef unsigned long long ull;

__device__ __forceinline__ ull fma2(ull a, ull b, ull c) {
    ull d;
    asm("fma.rn.f32x2 %0, %1, %2, %3;" : "=l"(d) : "l"(a), "l"(b), "l"(c));
    return d;
}
__device__ __forceinline__ ull add2(ull a, ull b) {
    ull d;
    asm("add.rn.f32x2 %0, %1, %2;" : "=l"(d) : "l"(a), "l"(b));
    return d;
}
__device__ __forceinline__ float2 unpack2(ull a) {
    float2 r;
    asm("mov.b64 {%0, %1}, %2;" : "=f"(r.x), "=f"(r.y) : "l"(a));
    return r;
}
// packed (bf16 lo, bf16 hi) -> f32x2 pair (exact: bf16 is top 16 bits of f32)
__device__ __forceinline__ ull bf2up(uint32_t r) {
    ull d;
    asm("{ .reg .b32 lo, hi;\n\t"
        "  shl.b32 lo, %1, 16;\n\t"
        "  and.b32 hi, %1, 0xFFFF0000;\n\t"
        "  mov.b64 %0, {lo, hi}; }"
        : "=l"(d) : "r"(r));
    return d;
}
__device__ __forceinline__ uint32_t tf32cvt(float x) {
    uint32_t u;
    asm("cvt.rna.tf32.f32 %0, %1;" : "=r"(u) : "f"(x));
    return u;
}
__device__ __forceinline__ void mma_tf32(float c[4],
                                         uint32_t a0, uint32_t a1, uint32_t a2, uint32_t a3,
                                         uint32_t b0, uint32_t b1) {
    asm("mma.sync.aligned.m16n8k8.row.col.f32.tf32.tf32.f32 "
        "{%0,%1,%2,%3},{%4,%5,%6,%7},{%8,%9},{%0,%1,%2,%3};"
        : "+f"(c[0]), "+f"(c[1]), "+f"(c[2]), "+f"(c[3])
        : "r"(a0), "r"(a1), "r"(a2), "r"(a3), "r"(b0), "r"(b1));
}

// ---------------- device scratch ----------------
__device__ float g_G [ (size_t)BB * TT * 1024 ];   // gate preactivations, both dirs
__device__ float g_H0[ (size_t)BB * TT * 256 ];
__device__ float g_H1[ (size_t)BB * TT * 256 ];
__device__ float g_E [ (size_t)BB * TT * 32 ];
__device__ float g_whT[ 4 * 128 * 512 ];           // [dl][k][512]
__device__ float g_wi0[ 1024 * 128 ];
__device__ float g_wi1[ 1024 * 256 ];
__device__ float g_b0 [ 1024 ];
__device__ float g_b1 [ 1024 ];
__device__ int   g_len[ BB ];

// ---------------- lengths ----------------
__global__ void len_kernel(const int* __restrict__ x)
{
    int b = blockIdx.x;
    __shared__ int cnt;
    if (threadIdx.x == 0) cnt = 0;
    __syncthreads();
    int local = 0;
    for (int t = threadIdx.x; t < TT; t += blockDim.x)
        local += (x[b * TT + t] > 0) ? 1 : 0;
    atomicAdd(&cnt, local);
    __syncthreads();
    if (threadIdx.x == 0) g_len[b] = cnt;
}

// ---------------- weight packing / transposition ----------------
__global__ void pack_kernel(const float* __restrict__ wi0f, const float* __restrict__ wi0b,
                            const float* __restrict__ b0f,  const float* __restrict__ b0b,
                            const float* __restrict__ wi1f, const float* __restrict__ wi1b,
                            const float* __restrict__ b1f,  const float* __restrict__ b1b,
                            const float* __restrict__ wh0f, const float* __restrict__ wh0b,
                            const float* __restrict__ wh1f, const float* __restrict__ wh1b)
{
    int tid = blockIdx.x * blockDim.x + threadIdx.x;
    int stride = gridDim.x * blockDim.x;
    for (int i = tid; i < 512 * 128; i += stride) {
        g_wi0[i]             = wi0f[i];
        g_wi0[512 * 128 + i] = wi0b[i];
    }
    for (int i = tid; i < 512 * 256; i += stride) {
        g_wi1[i]             = wi1f[i];
        g_wi1[512 * 256 + i] = wi1b[i];
    }
    for (int i = tid; i < 512; i += stride) {
        g_b0[i]       = b0f[i];
        g_b0[512 + i] = b0b[i];
        g_b1[i]       = b1f[i];
        g_b1[512 + i] = b1b[i];
    }
    const float* whs[4] = { wh0f, wh0b, wh1f, wh1b };
    for (int dl = 0; dl < 4; ++dl) {
        const float* w = whs[dl];
        for (int i = tid; i < 512 * 128; i += stride) {
            int r = i >> 7, k = i & 127;
            g_whT[dl * 65536 + k * 512 + r] = w[i];   // whT[k][r] = wh[r][k]
        }
    }
}

// ---------------- tf32 tensor-core GEMM: C[m][n] = sum_k A[m][k]*B[n][k] + bias[n] ----------------
// 64x64 CTA tile, 8 warps (4m x 2n), warp = 16x32, mma.sync m16n8k8 tf32.
// Skips blocks whose entire t-range is padding (output never consumed).
__global__ void __launch_bounds__(256, 1) gemm_kernel(const float* __restrict__ Ain,
                                                      const int* __restrict__ gidx,
                                                      int Kd, int phase)
{
    extern __shared__ uint32_t gsm[];
    uint32_t* As = gsm;                // 64 x 132 (tf32 bits)
    uint32_t* Bs = gsm + 64 * 132;     // 64 x 132

    int m0 = blockIdx.y * 64;
    int n0 = blockIdx.x * 64;

    {
        int b  = m0 >> 9;
        int t0 = m0 & 511;
        if (t0 >= g_len[b]) return;   // uniform across CTA, before any barrier
    }

    const float* A    = phase ? g_H0  : Ain;
    const float* Bw   = phase ? g_wi1 : g_wi0;
    const float* bias = phase ? g_b1  : g_b0;

    int tid  = threadIdx.x;
    int w    = tid >> 5;
    int lane = tid & 31;
    int wm   = w & 3;           // 0..3 -> m sub-tile
    int wn   = w >> 2;          // 0..1 -> n sub-tile
    int g    = lane >> 2;       // 0..7
    int t    = lane & 3;        // 0..3

    int lr  = tid >> 2;         // 0..63 load row
    int seg = (tid & 3) * 32;   // 0,32,64,96 load col segment

    size_t arow_idx = (size_t)(gidx ? gidx[m0 + lr] : (m0 + lr)) * Kd;
    size_t brow_idx = (size_t)(n0 + lr) * Kd;

    float acc[4][4] = {};

    int nch = Kd >> 7;          // K chunks of 128
    for (int ch = 0; ch < nch; ++ch) {
        const float* arow = A  + arow_idx + ch * 128 + seg;
        const float* brow = Bw + brow_idx + ch * 128 + seg;
        __syncthreads();
#pragma unroll
        for (int i = 0; i < 8; ++i) {
            float4 av = *(const float4*)(arow + 4 * i);
            float4 bv = *(const float4*)(brow + 4 * i);
            uint4 au = make_uint4(tf32cvt(av.x), tf32cvt(av.y), tf32cvt(av.z), tf32cvt(av.w));
            uint4 bu = make_uint4(tf32cvt(bv.x), tf32cvt(bv.y), tf32cvt(bv.z), tf32cvt(bv.w));
            *(uint4*)&As[lr * 132 + seg + 4 * i] = au;
            *(uint4*)&Bs[lr * 132 + seg + 4 * i] = bu;
        }
        __syncthreads();

        const uint32_t* Ar0 = &As[(wm * 16 + g)     * 132];
        const uint32_t* Ar1 = &As[(wm * 16 + g + 8) * 132];
#pragma unroll
        for (int ks = 0; ks < 16; ++ks) {
            int k0 = ks * 8 + t;
            uint32_t a0 = Ar0[k0];
            uint32_t a1 = Ar1[k0];
            uint32_t a2 = Ar0[k0 + 4];
            uint32_t a3 = Ar1[k0 + 4];
#pragma unroll
            for (int nt = 0; nt < 4; ++nt) {
                const uint32_t* Br = &Bs[(wn * 32 + nt * 8 + g) * 132];
                uint32_t b0 = Br[k0];
                uint32_t b1 = Br[k0 + 4];
                mma_tf32(acc[nt], a0, a1, a2, a3, b0, b1);
            }
        }
    }

    // epilogue: add bias, store fp32
    int mr0 = m0 + wm * 16 + g;
    int mr1 = mr0 + 8;
#pragma unroll
    for (int nt = 0; nt < 4; ++nt) {
        int nc = n0 + wn * 32 + nt * 8 + 2 * t;
        float2 bo = *(const float2*)&bias[nc];
        *(float2*)&g_G[(size_t)mr0 * 1024 + nc] = make_float2(acc[nt][0] + bo.x, acc[nt][1] + bo.y);
        *(float2*)&g_G[(size_t)mr1 * 1024 + nc] = make_float2(acc[nt][2] + bo.x, acc[nt][3] + bo.y);
    }
}

// ---------------- LSTM recurrence (R9, measured best) ----------------
__device__ __forceinline__ float tanh_mufu(float x) {
    float r;
    asm("tanh.approx.f32 %0, %1;" : "=f"(r) : "f"(x));
    return r;
}
__device__ __forceinline__ float sigm(float x) {
    return fmaf(0.5f, tanh_mufu(0.5f * x), 0.5f);
}

__global__ void __launch_bounds__(256, 1) lstm_kernel(int layer)
{
    int b   = blockIdx.x;
    int dir = blockIdx.y;
    const float* whT = g_whT + (size_t)(layer * 2 + dir) * 65536;  // [k][512]

    extern __shared__ float sm[];
    uint32_t* pwsb = (uint32_t*)sm;                    // KS*256 u32: packed bf16 row-pairs
    float* zbuf  = sm + (KS * 512 * 2) / 4;            // 512
    float* hpair = zbuf + 512;                         // 128 float2 (h duplicated)

    int tid = threadIdx.x;

    // pack smem weights to bf16 pairs: chunk c holds k-slices 4c..4c+3 for this thread
    for (int c = 0; c < KS / 4; ++c) {
        uint32_t v[4];
#pragma unroll
        for (int j = 0; j < 4; ++j) {
            float2 w = *(const float2*)&whT[(4 * c + j) * 512 + 2 * tid];
            __nv_bfloat162 bb = __float22bfloat162_rn(w);
            v[j] = *(uint32_t*)&bb;
        }
        *(uint4*)&pwsb[(c * 256 + tid) * 4] = make_uint4(v[0], v[1], v[2], v[3]);
    }

    ull tw[TAILK];
#pragma unroll
    for (int j = 0; j < TAILK; ++j)
        tw[j] = *(const ull*)&whT[(KS + j) * 512 + 2 * tid];

    if (tid < 128) *(float2*)&hpair[2 * tid] = make_float2(0.f, 0.f);
    float c_st = 0.f;
    int len = g_len[b];
    float* Hout = layer ? g_H1 : g_H0;
    __syncthreads();

    const ulonglong2* hp = (const ulonglong2*)hpair;

    int t = (dir == 0) ? 0 : (len - 1);
    ull gc = *(const ull*)&g_G[((size_t)(b * TT + t)) * 1024 + dir * 512 + 2 * tid];

    for (int s = 0; s < len; ++s) {
        int sn = s + 1;
        int tnx;
        if (dir == 0) tnx = sn;
        else          tnx = len - 1 - sn;
        if (sn >= len) tnx = t;   // dummy (value unused on last iter)
        ull gn = *(const ull*)&g_G[((size_t)(b * TT + tnx)) * 1024 + dir * 512 + 2 * tid];

        ull acc0 = gc, acc1 = 0, acc2 = 0, acc3 = 0;
#pragma unroll
        for (int c = 0; c < KS / 4; ++c) {
            uint4 w4 = *(const uint4*)&pwsb[(c * 256 + tid) * 4];
            ulonglong2 hv0 = hp[2 * c];
            ulonglong2 hv1 = hp[2 * c + 1];
            acc0 = fma2(bf2up(w4.x), hv0.x, acc0);
            acc1 = fma2(bf2up(w4.y), hv0.y, acc1);
            acc2 = fma2(bf2up(w4.z), hv1.x, acc2);
            acc3 = fma2(bf2up(w4.w), hv1.y, acc3);
        }
#pragma unroll
        for (int j = 0; j < TAILK; j += 2) {
            ulonglong2 hv = hp[(KS + j) >> 1];
            acc0 = fma2(tw[j],     hv.x, acc0);
            acc1 = fma2(tw[j + 1], hv.y, acc1);
        }
        float2 z = unpack2(add2(add2(acc0, acc1), add2(acc2, acc3)));
        *(float2*)&zbuf[2 * tid] = z;
        __syncthreads();

        if (tid < 128) {
            float zi = zbuf[tid],       zf = zbuf[128 + tid];
            float zg = zbuf[256 + tid], zo = zbuf[384 + tid];
            c_st = sigm(zf) * c_st + sigm(zi) * tanh_mufu(zg);
            float h = sigm(zo) * tanh_mufu(c_st);
            *(float2*)&hpair[2 * tid] = make_float2(h, h);
            Hout[((size_t)(b * TT + t)) * 256 + dir * 128 + tid] = h;
        }
        __syncthreads();
        gc = gn;
        t  = tnx;
    }
}

// ---------------- emissions: e = H1 @ w_out^T + b_out ----------------
__global__ void emis_kernel(const float* __restrict__ w_out, const float* __restrict__ b_out)
{
    __shared__ float ws[32 * 257];
    __shared__ float hs[8][256];
    __shared__ float bs[32];

    int tid = threadIdx.x;
    for (int i = tid; i < 32 * 256; i += 256)
        ws[(i >> 8) * 257 + (i & 255)] = w_out[i];
    if (tid < 32) bs[tid] = b_out[tid];

    int w    = tid >> 5;
    int lane = tid & 31;
    int m    = blockIdx.x * 8 + w;
    for (int d = lane; d < 256; d += 32)
        hs[w][d] = g_H1[(size_t)m * 256 + d];
    __syncthreads();

    float e = bs[lane];
#pragma unroll 8
    for (int d = 0; d < 256; ++d)
        e += hs[w][d] * ws[lane * 257 + d];
    g_E[(size_t)m * 32 + lane] = e;
}

// ---------------- CRF: warp per batch ----------------
__global__ void crf_kernel(const int* __restrict__ y, const float* __restrict__ trans,
                           float* __restrict__ out)
{
    int b    = blockIdx.x;
    int lane = threadIdx.x;
    __shared__ float tr[32 * 33];
    for (int i = lane; i < 1024; i += 32)
        tr[(i >> 5) * 33 + (i & 31)] = trans[i];
    __syncwarp();

    int len = g_len[b];
    const float* Eb = g_E + (size_t)b * TT * 32;

    float score = (lane == SOS) ? 0.f : -10000.f;
    for (int t = 0; t < len; ++t) {
        float e = Eb[t * 32 + lane];
        float v[32];
#pragma unroll
        for (int k = 0; k < 32; ++k)
            v[k] = __shfl_sync(0xffffffffu, score, k) + tr[lane * 33 + k];
        float m = v[0];
#pragma unroll
        for (int k = 1; k < 32; ++k) m = fmaxf(m, v[k]);
        float s = 0.f;
#pragma unroll
        for (int k = 0; k < 32; ++k) s += expf(v[k] - m);
        score = e + m + logf(s);
    }

    float v2 = score + tr[EOS * 33 + lane];
    float m = v2;
#pragma unroll
    for (int off = 16; off; off >>= 1) m = fmaxf(m, __shfl_xor_sync(0xffffffffu, m, off));
    float s = expf(v2 - m);
#pragma unroll
    for (int off = 16; off; off >>= 1) s += __shfl_xor_sync(0xffffffffu, s, off);
    float logZ = m + logf(s);

    const int* yb = y + b * (TT + 1);
    float g = 0.f;
    for (int t = lane; t < len; t += 32) {
        int y1 = yb[t + 1];
        int y0 = yb[t];
        g += Eb[t * 32 + y1] + tr[y1 * 33 + y0];
    }
#pragma unroll
    for (int off = 16; off; off >>= 1) g += __shfl_xor_sync(0xffffffffu, g, off);

    if (lane == 0) {
        g += tr[EOS * 33 + yb[len]];
        out[b] = logZ - g;
    }
}

// ---------------- launch ----------------
extern "C" void kernel_launch(void* const* d_in, const int* in_sizes, int n_in,
                              void* d_out, int out_size)
{
    const int*   x      = (const int*)  d_in[0];
    const int*   y      = (const int*)  d_in[1];
    const float* embed  = (const float*)d_in[2];
    const float* wi_l0f = (const float*)d_in[3];
    const float* wh_l0f = (const float*)d_in[4];
    const float* b_l0f  = (const float*)d_in[5];
    const float* wi_l0b = (const float*)d_in[6];
    const float* wh_l0b = (const float*)d_in[7];
    const float* b_l0b  = (const float*)d_in[8];
    const float* wi_l1f = (const float*)d_in[9];
    const float* wh_l1f = (const float*)d_in[10];
    const float* b_l1f  = (const float*)d_in[11];
    const float* wi_l1b = (const float*)d_in[12];
    const float* wh_l1b = (const float*)d_in[13];
    const float* b_l1b  = (const float*)d_in[14];
    const float* w_out  = (const float*)d_in[15];
    const float* b_out  = (const float*)d_in[16];
    const float* trans  = (const float*)d_in[17];
    float* out = (float*)d_out;

    cudaFuncSetAttribute(lstm_kernel, cudaFuncAttributeMaxDynamicSharedMemorySize, LSTM_SMEM);
    cudaFuncSetAttribute(gemm_kernel, cudaFuncAttributeMaxDynamicSharedMemorySize, GEMM_SMEM);

    len_kernel<<<BB, 256>>>(x);
    pack_kernel<<<256, 256>>>(wi_l0f, wi_l0b, b_l0f, b_l0b,
                              wi_l1f, wi_l1b, b_l1f, b_l1b,
                              wh_l0f, wh_l0b, wh_l1f, wh_l1b);

    gemm_kernel<<<dim3(16, 512), 256, GEMM_SMEM>>>(embed, x, 128, 0);
    lstm_kernel<<<dim3(BB, 2), 256, LSTM_SMEM>>>(0);

    gemm_kernel<<<dim3(16, 512), 256, GEMM_SMEM>>>(nullptr, nullptr, 256, 1);
    lstm_kernel<<<dim3(BB, 2), 256, LSTM_SMEM>>>(1);

    emis_kernel<<<(BB * TT) / 8, 256>>>(w_out, b_out);
    crf_kernel<<<BB, 32>>>(y, trans, out);
}

// round 12
// speedup vs baseline: 1.4646x; 1.0428x over previous
#include <cuda_runtime.h>
#include <cuda_bf16.h>
#include <math.h>
#include <stdint.h>

// Problem constants
#define BB   64
#define TT   512
#define EE   128
#define HH   256
#define HP   128
#define KK   32
#define SOS  2
#define EOS  3

// LSTM recurrence split: KS h-slices of wh in smem (bf16), TAILK in registers (fp32)
#define KS    48
#define TAILK 80
#define LSTM_SMEM (KS*512*2 + (512 + 256) * 4)

// GEMM tile smem: two 64x128 tiles padded to 132 words/row
#define GEMM_SMEM (2 * 64 * 132 * 4)

typedef unsigned long long ull;

__device__ __forceinline__ ull fma2(ull a, ull b, ull c) {
    ull d;
    asm("fma.rn.f32x2 %0, %1, %2, %3;" : "=l"(d) : "l"(a), "l"(b), "l"(c));
    return d;
}
__device__ __forceinline__ ull add2(ull a, ull b) {
    ull d;
    asm("add.rn.f32x2 %0, %1, %2;" : "=l"(d) : "l"(a), "l"(b));
    return d;
}
__device__ __forceinline__ float2 unpack2(ull a) {
    float2 r;
    asm("mov.b64 {%0, %1}, %2;" : "=f"(r.x), "=f"(r.y) : "l"(a));
    return r;
}
// packed (bf16 lo, bf16 hi) -> f32x2 pair (exact: bf16 is top 16 bits of f32)
__device__ __forceinline__ ull bf2up(uint32_t r) {
    ull d;
    asm("{ .reg .b32 lo, hi;\n\t"
        "  shl.b32 lo, %1, 16;\n\t"
        "  and.b32 hi, %1, 0xFFFF0000;\n\t"
        "  mov.b64 %0, {lo, hi}; }"
        : "=l"(d) : "r"(r));
    return d;
}
__device__ __forceinline__ uint32_t tf32cvt(float x) {
    uint32_t u;
    asm("cvt.rna.tf32.f32 %0, %1;" : "=r"(u) : "f"(x));
    return u;
}
__device__ __forceinline__ void mma_tf32(float c[4],
                                         uint32_t a0, uint32_t a1, uint32_t a2, uint32_t a3,
                                         uint32_t b0, uint32_t b1) {
    asm("mma.sync.aligned.m16n8k8.row.col.f32.tf32.tf32.f32 "
        "{%0,%1,%2,%3},{%4,%5,%6,%7},{%8,%9},{%0,%1,%2,%3};"
        : "+f"(c[0]), "+f"(c[1]), "+f"(c[2]), "+f"(c[3])
        : "r"(a0), "r"(a1), "r"(a2), "r"(a3), "r"(b0), "r"(b1));
}

// ---------------- device scratch ----------------
__device__ float g_G [ (size_t)BB * TT * 1024 ];   // gate preactivations, both dirs
__device__ float g_H0[ (size_t)BB * TT * 256 ];
__device__ float g_H1[ (size_t)BB * TT * 256 ];
__device__ float g_E [ (size_t)BB * TT * 32 ];
__device__ float g_whT[ 4 * 128 * 512 ];           // [dl][k][512]
__device__ float g_wi0[ 1024 * 128 ];
__device__ float g_wi1[ 1024 * 256 ];
__device__ float g_b0 [ 1024 ];
__device__ float g_b1 [ 1024 ];
__device__ int   g_len[ BB ];

// ---------------- lengths ----------------
__global__ void len_kernel(const int* __restrict__ x)
{
    int b = blockIdx.x;
    __shared__ int cnt;
    if (threadIdx.x == 0) cnt = 0;
    __syncthreads();
    int local = 0;
    for (int t = threadIdx.x; t < TT; t += blockDim.x)
        local += (x[b * TT + t] > 0) ? 1 : 0;
    atomicAdd(&cnt, local);
    __syncthreads();
    if (threadIdx.x == 0) g_len[b] = cnt;
}

// ---------------- weight packing (split for profiling slot alignment) ----------------
__global__ void pack_wi_kernel(const float* __restrict__ wi0f, const float* __restrict__ wi0b,
                               const float* __restrict__ b0f,  const float* __restrict__ b0b,
                               const float* __restrict__ wi1f, const float* __restrict__ wi1b,
                               const float* __restrict__ b1f,  const float* __restrict__ b1b)
{
    int tid = blockIdx.x * blockDim.x + threadIdx.x;
    int stride = gridDim.x * blockDim.x;
    for (int i = tid; i < 512 * 128; i += stride) {
        g_wi0[i]             = wi0f[i];
        g_wi0[512 * 128 + i] = wi0b[i];
    }
    for (int i = tid; i < 512 * 256; i += stride) {
        g_wi1[i]             = wi1f[i];
        g_wi1[512 * 256 + i] = wi1b[i];
    }
    for (int i = tid; i < 512; i += stride) {
        g_b0[i]       = b0f[i];
        g_b0[512 + i] = b0b[i];
        g_b1[i]       = b1f[i];
        g_b1[512 + i] = b1b[i];
    }
}

__global__ void pack_wh_kernel(const float* __restrict__ wh0f, const float* __restrict__ wh0b,
                               const float* __restrict__ wh1f, const float* __restrict__ wh1b)
{
    int tid = blockIdx.x * blockDim.x + threadIdx.x;
    int stride = gridDim.x * blockDim.x;
    const float* whs[4] = { wh0f, wh0b, wh1f, wh1b };
    for (int dl = 0; dl < 4; ++dl) {
        const float* w = whs[dl];
        for (int i = tid; i < 512 * 128; i += stride) {
            int r = i >> 7, k = i & 127;
            g_whT[dl * 65536 + k * 512 + r] = w[i];   // whT[k][r] = wh[r][k]
        }
    }
}

// ---------------- tf32 tensor-core GEMM: C[m][n] = sum_k A[m][k]*B[n][k] + bias[n] ----------------
__global__ void __launch_bounds__(256, 1) gemm_kernel(const float* __restrict__ Ain,
                                                      const int* __restrict__ gidx,
                                                      int Kd, int phase)
{
    extern __shared__ uint32_t gsm[];
    uint32_t* As = gsm;                // 64 x 132 (tf32 bits)
    uint32_t* Bs = gsm + 64 * 132;     // 64 x 132

    int m0 = blockIdx.y * 64;
    int n0 = blockIdx.x * 64;

    {
        int b  = m0 >> 9;
        int t0 = m0 & 511;
        if (t0 >= g_len[b]) return;   // uniform across CTA, before any barrier
    }

    const float* A    = phase ? g_H0  : Ain;
    const float* Bw   = phase ? g_wi1 : g_wi0;
    const float* bias = phase ? g_b1  : g_b0;

    int tid  = threadIdx.x;
    int w    = tid >> 5;
    int lane = tid & 31;
    int wm   = w & 3;           // 0..3 -> m sub-tile
    int wn   = w >> 2;          // 0..1 -> n sub-tile
    int g    = lane >> 2;       // 0..7
    int t    = lane & 3;        // 0..3

    int lr  = tid >> 2;         // 0..63 load row
    int seg = (tid & 3) * 32;   // 0,32,64,96 load col segment

    size_t arow_idx = (size_t)(gidx ? gidx[m0 + lr] : (m0 + lr)) * Kd;
    size_t brow_idx = (size_t)(n0 + lr) * Kd;

    float acc[4][4] = {};

    int nch = Kd >> 7;          // K chunks of 128
    for (int ch = 0; ch < nch; ++ch) {
        const float* arow = A  + arow_idx + ch * 128 + seg;
        const float* brow = Bw + brow_idx + ch * 128 + seg;
        __syncthreads();
#pragma unroll
        for (int i = 0; i < 8; ++i) {
            float4 av = *(const float4*)(arow + 4 * i);
            float4 bv = *(const float4*)(brow + 4 * i);
            uint4 au = make_uint4(tf32cvt(av.x), tf32cvt(av.y), tf32cvt(av.z), tf32cvt(av.w));
            uint4 bu = make_uint4(tf32cvt(bv.x), tf32cvt(bv.y), tf32cvt(bv.z), tf32cvt(bv.w));
            *(uint4*)&As[lr * 132 + seg + 4 * i] = au;
            *(uint4*)&Bs[lr * 132 + seg + 4 * i] = bu;
        }
        __syncthreads();

        const uint32_t* Ar0 = &As[(wm * 16 + g)     * 132];
        const uint32_t* Ar1 = &As[(wm * 16 + g + 8) * 132];
#pragma unroll
        for (int ks = 0; ks < 16; ++ks) {
            int k0 = ks * 8 + t;
            uint32_t a0 = Ar0[k0];
            uint32_t a1 = Ar1[k0];
            uint32_t a2 = Ar0[k0 + 4];
            uint32_t a3 = Ar1[k0 + 4];
#pragma unroll
            for (int nt = 0; nt < 4; ++nt) {
                const uint32_t* Br = &Bs[(wn * 32 + nt * 8 + g) * 132];
                uint32_t b0 = Br[k0];
                uint32_t b1 = Br[k0 + 4];
                mma_tf32(acc[nt], a0, a1, a2, a3, b0, b1);
            }
        }
    }

    int mr0 = m0 + wm * 16 + g;
    int mr1 = mr0 + 8;
#pragma unroll
    for (int nt = 0; nt < 4; ++nt) {
        int nc = n0 + wn * 32 + nt * 8 + 2 * t;
        float2 bo = *(const float2*)&bias[nc];
        *(float2*)&g_G[(size_t)mr0 * 1024 + nc] = make_float2(acc[nt][0] + bo.x, acc[nt][1] + bo.y);
        *(float2*)&g_G[(size_t)mr1 * 1024 + nc] = make_float2(acc[nt][2] + bo.x, acc[nt][3] + bo.y);
    }
}

// ---------------- LSTM recurrence (R9, measured best) ----------------
__device__ __forceinline__ float tanh_mufu(float x) {
    float r;
    asm("tanh.approx.f32 %0, %1;" : "=f"(r) : "f"(x));
    return r;
}
__device__ __forceinline__ float sigm(float x) {
    return fmaf(0.5f, tanh_mufu(0.5f * x), 0.5f);
}

__global__ void __launch_bounds__(256, 1) lstm_kernel(int layer)
{
    int b   = blockIdx.x;
    int dir = blockIdx.y;
    const float* whT = g_whT + (size_t)(layer * 2 + dir) * 65536;  // [k][512]

    extern __shared__ float sm[];
    uint32_t* pwsb = (uint32_t*)sm;                    // KS*256 u32: packed bf16 row-pairs
    float* zbuf  = sm + (KS * 512 * 2) / 4;            // 512
    float* hpair = zbuf + 512;                         // 128 float2 (h duplicated)

    int tid = threadIdx.x;

    for (int c = 0; c < KS / 4; ++c) {
        uint32_t v[4];
#pragma unroll
        for (int j = 0; j < 4; ++j) {
            float2 w = *(const float2*)&whT[(4 * c + j) * 512 + 2 * tid];
            __nv_bfloat162 bb = __float22bfloat162_rn(w);
            v[j] = *(uint32_t*)&bb;
        }
        *(uint4*)&pwsb[(c * 256 + tid) * 4] = make_uint4(v[0], v[1], v[2], v[3]);
    }

    ull tw[TAILK];
#pragma unroll
    for (int j = 0; j < TAILK; ++j)
        tw[j] = *(const ull*)&whT[(KS + j) * 512 + 2 * tid];

    if (tid < 128) *(float2*)&hpair[2 * tid] = make_float2(0.f, 0.f);
    float c_st = 0.f;
    int len = g_len[b];
    float* Hout = layer ? g_H1 : g_H0;
    __syncthreads();

    const ulonglong2* hp = (const ulonglong2*)hpair;

    int t = (dir == 0) ? 0 : (len - 1);
    ull gc = *(const ull*)&g_G[((size_t)(b * TT + t)) * 1024 + dir * 512 + 2 * tid];

    for (int s = 0; s < len; ++s) {
        int sn = s + 1;
        int tnx;
        if (dir == 0) tnx = sn;
        else          tnx = len - 1 - sn;
        if (sn >= len) tnx = t;   // dummy (value unused on last iter)
        ull gn = *(const ull*)&g_G[((size_t)(b * TT + tnx)) * 1024 + dir * 512 + 2 * tid];

        ull acc0 = gc, acc1 = 0, acc2 = 0, acc3 = 0;
#pragma unroll
        for (int c = 0; c < KS / 4; ++c) {
            uint4 w4 = *(const uint4*)&pwsb[(c * 256 + tid) * 4];
            ulonglong2 hv0 = hp[2 * c];
            ulonglong2 hv1 = hp[2 * c + 1];
            acc0 = fma2(bf2up(w4.x), hv0.x, acc0);
            acc1 = fma2(bf2up(w4.y), hv0.y, acc1);
            acc2 = fma2(bf2up(w4.z), hv1.x, acc2);
            acc3 = fma2(bf2up(w4.w), hv1.y, acc3);
        }
#pragma unroll
        for (int j = 0; j < TAILK; j += 2) {
            ulonglong2 hv = hp[(KS + j) >> 1];
            acc0 = fma2(tw[j],     hv.x, acc0);
            acc1 = fma2(tw[j + 1], hv.y, acc1);
        }
        float2 z = unpack2(add2(add2(acc0, acc1), add2(acc2, acc3)));
        *(float2*)&zbuf[2 * tid] = z;
        __syncthreads();

        if (tid < 128) {
            float zi = zbuf[tid],       zf = zbuf[128 + tid];
            float zg = zbuf[256 + tid], zo = zbuf[384 + tid];
            c_st = sigm(zf) * c_st + sigm(zi) * tanh_mufu(zg);
            float h = sigm(zo) * tanh_mufu(c_st);
            *(float2*)&hpair[2 * tid] = make_float2(h, h);
            Hout[((size_t)(b * TT + t)) * 256 + dir * 128 + tid] = h;
        }
        __syncthreads();
        gc = gn;
        t  = tnx;
    }
}

// ---------------- emissions: e = H1 @ w_out^T + b_out ----------------
__global__ void emis_kernel(const float* __restrict__ w_out, const float* __restrict__ b_out)
{
    __shared__ float ws[32 * 257];
    __shared__ float hs[8][256];
    __shared__ float bs[32];

    int tid = threadIdx.x;
    for (int i = tid; i < 32 * 256; i += 256)
        ws[(i >> 8) * 257 + (i & 255)] = w_out[i];
    if (tid < 32) bs[tid] = b_out[tid];

    int w    = tid >> 5;
    int lane = tid & 31;
    int m    = blockIdx.x * 8 + w;
    for (int d = lane; d < 256; d += 32)
        hs[w][d] = g_H1[(size_t)m * 256 + d];
    __syncthreads();

    float e = bs[lane];
#pragma unroll 8
    for (int d = 0; d < 256; ++d)
        e += hs[w][d] * ws[lane * 257 + d];
    g_E[(size_t)m * 32 + lane] = e;
}

// ---------------- CRF: warp per batch, exp-space inner loop ----------------
__global__ void crf_kernel(const int* __restrict__ y, const float* __restrict__ trans,
                           float* __restrict__ out)
{
    int b    = blockIdx.x;
    int lane = threadIdx.x;
    __shared__ float tr[32 * 33];
    for (int i = lane; i < 1024; i += 32)
        tr[(i >> 5) * 33 + (i & 31)] = trans[i];
    __syncwarp();

    // preload exp(trans[lane][k]) into registers (exp(-10000) -> 0 exactly)
    float etr[32];
#pragma unroll
    for (int k = 0; k < 32; ++k)
        etr[k] = __expf(tr[lane * 33 + k]);

    int len = g_len[b];
    const float* Eb = g_E + (size_t)b * TT * 32;

    float score = (lane == SOS) ? 0.f : -10000.f;
    for (int t = 0; t < len; ++t) {
        float e = Eb[t * 32 + lane];
        // m = max over lanes of score
        float m = score;
#pragma unroll
        for (int off = 16; off; off >>= 1)
            m = fmaxf(m, __shfl_xor_sync(0xffffffffu, m, off));
        float es = __expf(score - m);
        float s = 0.f;
#pragma unroll
        for (int k = 0; k < 32; ++k)
            s = fmaf(etr[k], __shfl_sync(0xffffffffu, es, k), s);
        score = e + m + __logf(s);
    }

    float v2 = score + tr[EOS * 33 + lane];
    float m = v2;
#pragma unroll
    for (int off = 16; off; off >>= 1) m = fmaxf(m, __shfl_xor_sync(0xffffffffu, m, off));
    float s = expf(v2 - m);
#pragma unroll
    for (int off = 16; off; off >>= 1) s += __shfl_xor_sync(0xffffffffu, s, off);
    float logZ = m + logf(s);

    const int* yb = y + b * (TT + 1);
    float g = 0.f;
    for (int t = lane; t < len; t += 32) {
        int y1 = yb[t + 1];
        int y0 = yb[t];
        g += Eb[t * 32 + y1] + tr[y1 * 33 + y0];
    }
#pragma unroll
    for (int off = 16; off; off >>= 1) g += __shfl_xor_sync(0xffffffffu, g, off);

    if (lane == 0) {
        g += tr[EOS * 33 + yb[len]];
        out[b] = logZ - g;
    }
}

// ---------------- launch ----------------
extern "C" void kernel_launch(void* const* d_in, const int* in_sizes, int n_in,
                              void* d_out, int out_size)
{
    const int*   x      = (const int*)  d_in[0];
    const int*   y      = (const int*)  d_in[1];
    const float* embed  = (const float*)d_in[2];
    const float* wi_l0f = (const float*)d_in[3];
    const float* wh_l0f = (const float*)d_in[4];
    const float* b_l0f  = (const float*)d_in[5];
    const float* wi_l0b = (const float*)d_in[6];
    const float* wh_l0b = (const float*)d_in[7];
    const float* b_l0b  = (const float*)d_in[8];
    const float* wi_l1f = (const float*)d_in[9];
    const float* wh_l1f = (const float*)d_in[10];
    const float* b_l1f  = (const float*)d_in[11];
    const float* wi_l1b = (const float*)d_in[12];
    const float* wh_l1b = (const float*)d_in[13];
    const float* b_l1b  = (const float*)d_in[14];
    const float* w_out  = (const float*)d_in[15];
    const float* b_out  = (const float*)d_in[16];
    const float* trans  = (const float*)d_in[17];
    float* out = (float*)d_out;

    cudaFuncSetAttribute(lstm_kernel, cudaFuncAttributeMaxDynamicSharedMemorySize, LSTM_SMEM);
    cudaFuncSetAttribute(gemm_kernel, cudaFuncAttributeMaxDynamicSharedMemorySize, GEMM_SMEM);

    len_kernel<<<BB, 256>>>(x);                                   // launch 1
    pack_wi_kernel<<<256, 256>>>(wi_l0f, wi_l0b, b_l0f, b_l0b,
                                 wi_l1f, wi_l1b, b_l1f, b_l1b);   // launch 2
    pack_wh_kernel<<<256, 256>>>(wh_l0f, wh_l0b, wh_l1f, wh_l1b); // launch 3

    gemm_kernel<<<dim3(16, 512), 256, GEMM_SMEM>>>(embed, x, 128, 0);   // launch 4
    lstm_kernel<<<dim3(BB, 2), 256, LSTM_SMEM>>>(0);                    // launch 5

    gemm_kernel<<<dim3(16, 512), 256, GEMM_SMEM>>>(nullptr, nullptr, 256, 1); // launch 6 (profiled)
    lstm_kernel<<<dim3(BB, 2), 256, LSTM_SMEM>>>(1);

    emis_kernel<<<(BB * TT) / 8, 256>>>(w_out, b_out);
    crf_kernel<<<BB, 32>>>(y, trans, out);
}